// round 9
// baseline (speedup 1.0000x reference)
#include <cuda_runtime.h>
#include <cstdint>

#define FD 1024
#define RD 64
#define MT 128
#define NCH 16          // GEMM1 chunks of 64 cols

// ---------------- device scratch ----------------
__device__ float g_Gp[8][RD * RD];      // partial Gram matrices (no atomics)
__device__ float g_Minv[RD * RD];
__device__ uint4 g_PP[64 * 8 * 32];     // GEMM1 B frags: [kstep][ntile][lane] {h0,h1,l0,l1}
__device__ uint4 g_WP[128 * 4 * 32];    // GEMM2 B frags: [ntile][kstep][lane]
__device__ uint4 g_MP[8 * 4 * 32];      // d3 B frags (Minv)

// ---------------- helpers ----------------
__device__ __forceinline__ void split2(float x, float y, uint32_t& hi, uint32_t& lo) {
    asm("cvt.rn.bf16x2.f32 %0, %1, %2;" : "=r"(hi) : "f"(y), "f"(x));
    float xr = x - __uint_as_float(hi << 16);
    float yr = y - __uint_as_float(hi & 0xffff0000u);
    asm("cvt.rn.bf16x2.f32 %0, %1, %2;" : "=r"(lo) : "f"(yr), "f"(xr));
}

__device__ __forceinline__ void mma_bf16(float* d,
    uint32_t a0, uint32_t a1, uint32_t a2, uint32_t a3,
    uint32_t b0, uint32_t b1) {
    asm volatile("mma.sync.aligned.m16n8k16.row.col.f32.bf16.bf16.f32 "
        "{%0,%1,%2,%3}, {%4,%5,%6,%7}, {%8,%9}, {%0,%1,%2,%3};"
        : "+f"(d[0]), "+f"(d[1]), "+f"(d[2]), "+f"(d[3])
        : "r"(a0), "r"(a1), "r"(a2), "r"(a3), "r"(b0), "r"(b1));
}

__device__ __forceinline__ void cpa16(uint32_t s, const void* g) {
    asm volatile("cp.async.cg.shared.global [%0], [%1], 16;" :: "r"(s), "l"(g));
}
#define CP_COMMIT asm volatile("cp.async.commit_group;" ::: "memory")
#define CP_WAIT0  asm volatile("cp.async.wait_group 0;" ::: "memory")

// ---------------- prep kernel 1: partial gram (blocks 0-7) + pack P (all 64) ----------------
__global__ void k_prep1(const float* __restrict__ probe) {
    __shared__ float Ps[128][68];
    int t = threadIdx.x;
    if (blockIdx.x < 8) {
        int c = blockIdx.x;
        #pragma unroll
        for (int i = 0; i < 8; i++) {
            int idx = t + 256 * i;
            int fl = idx >> 4, r4 = (idx & 15) << 2;
            float4 v = *(const float4*)(probe + (c * 128 + fl) * 64 + r4);
            *(float4*)(&Ps[fl][r4]) = v;
        }
        __syncthreads();
        int ti = (t >> 4) << 2, tj = (t & 15) << 2;
        float acc[4][4];
        #pragma unroll
        for (int a = 0; a < 4; a++)
            #pragma unroll
            for (int b = 0; b < 4; b++) acc[a][b] = 0.f;
        for (int k = 0; k < 128; k++) {
            float av[4], bv[4];
            #pragma unroll
            for (int a = 0; a < 4; a++) av[a] = Ps[k][ti + a];
            #pragma unroll
            for (int b = 0; b < 4; b++) bv[b] = Ps[k][tj + b];
            #pragma unroll
            for (int a = 0; a < 4; a++)
                #pragma unroll
                for (int b = 0; b < 4; b++) acc[a][b] = fmaf(av[a], bv[b], acc[a][b]);
        }
        #pragma unroll
        for (int a = 0; a < 4; a++)
            #pragma unroll
            for (int b = 0; b < 4; b++)
                g_Gp[c][(ti + a) * 64 + tj + b] = acc[a][b];
    }
    {
        int id = blockIdx.x * 256 + t;
        int lane = id & 31, g = lane >> 2, tq = lane & 3;
        int kk = id >> 8, j = (id >> 5) & 7;
        int n = 8 * j + g, k0 = 16 * kk + 2 * tq;
        float p00 = probe[(k0) * 64 + n], p01 = probe[(k0 + 1) * 64 + n];
        float p10 = probe[(k0 + 8) * 64 + n], p11 = probe[(k0 + 9) * 64 + n];
        uint32_t h0, l0, h1, l1;
        split2(p00, p01, h0, l0);
        split2(p10, p11, h1, l1);
        g_PP[id] = make_uint4(h0, h1, l0, l1);
    }
}

// ---------------- prep kernel 2: sum partials, invert, pack Minv frags ----------------
__global__ void k_inv() {
    __shared__ float A[64][129];
    int r = threadIdx.x;
    for (int j = 0; j < 64; j++) {
        float s = 0.f;
        #pragma unroll
        for (int c = 0; c < 8; c++) s += g_Gp[c][r * 64 + j];
        A[r][j] = s;
    }
    for (int j = 0; j < 64; j++) A[r][64 + j] = (r == j) ? 1.f : 0.f;
    __syncthreads();
    for (int k = 0; k < 64; k++) {
        if (r == k) {
            float inv = 1.f / A[k][k];
            for (int j = 0; j < 128; j++) A[k][j] *= inv;
        }
        __syncthreads();
        if (r != k) {
            float f = A[r][k];
            for (int j = 0; j < 128; j++) A[r][j] = fmaf(-f, A[k][j], A[r][j]);
        }
        __syncthreads();
    }
    for (int j = 0; j < 64; j++) g_Minv[r * 64 + j] = A[r][64 + j];
    // pack g_MP from smem (1024 uint4, 16 per thread)
    for (int i = 0; i < 16; i++) {
        int id = r + 64 * i;
        int lane = id & 31, g = lane >> 2, tq = lane & 3;
        int j = id >> 7, kk = (id >> 5) & 3;
        int n = 8 * j + g, k0 = 16 * kk + 2 * tq;
        float m00 = A[k0][64 + n],     m01 = A[k0 + 1][64 + n];
        float m10 = A[k0 + 8][64 + n], m11 = A[k0 + 9][64 + n];
        uint32_t h0, l0, h1, l1;
        split2(m00, m01, h0, l0);
        split2(m10, m11, h1, l1);
        g_MP[id] = make_uint4(h0, h1, l0, l1);
    }
}

// ---------------- prep kernel 3: W = P*Minv for 8 f-rows/block + pack W frags ----------------
__global__ void k_w(const float* __restrict__ probe) {
    __shared__ float Ms[64 * 64];
    __shared__ float Ps[8][64];
    __shared__ float Ws[8][64];
    int t = threadIdx.x;               // 512 threads
    for (int i = t; i < 4096; i += 512) Ms[i] = g_Minv[i];
    {
        int fl = t >> 6, k = t & 63;
        Ps[fl][k] = probe[(blockIdx.x * 8 + fl) * 64 + k];
    }
    __syncthreads();
    {
        int fl = t >> 6, r = t & 63;
        float acc = 0.f;
        #pragma unroll 16
        for (int k = 0; k < 64; k++) acc = fmaf(Ps[fl][k], Ms[k * 64 + r], acc);
        Ws[fl][r] = acc;
    }
    __syncthreads();
    if (t < 128) {
        int kk = t >> 5, lane = t & 31, g = lane >> 2, tq = lane & 3;
        int r0 = 16 * kk + 2 * tq;
        float w00 = Ws[g][r0],     w01 = Ws[g][r0 + 1];
        float w10 = Ws[g][r0 + 8], w11 = Ws[g][r0 + 9];
        uint32_t h0, l0, h1, l1;
        split2(w00, w01, h0, l0);
        split2(w10, w11, h1, l1);
        g_WP[blockIdx.x * 128 + kk * 32 + lane] = make_uint4(h0, h1, l0, l1);
    }
}

// ---------------- main kernel ----------------
#define SMEM_WORDS 16448
#define SMEM_BYTES (SMEM_WORDS * 4)

__global__ void __launch_bounds__(256, 2)
k_main(const float* __restrict__ hs, float* __restrict__ out) {
    extern __shared__ uint32_t smw[];
    uint4* Bs = (uint4*)smw;

    const int t = threadIdx.x;
    const int wg = t >> 5, lane = t & 31, g = lane >> 2, tq = lane & 3;
    const size_t g0 = (size_t)blockIdx.x * MT;
    const size_t rowA = g0 + 16 * wg + g, rowB = rowA + 8;
    const float* hA = hs + rowA * FD;
    const float* hB = hs + rowB * FD;

    uint32_t sbase = (uint32_t)__cvta_generic_to_shared(smw);

    // prologue: stage GEMM1 B chunk 0 -> buf0
    #pragma unroll
    for (int q = 0; q < 4; q++)
        cpa16(sbase + (t + 256 * q) * 16, g_PP + t + 256 * q);
    CP_COMMIT;

    float acc1[8][4];
    #pragma unroll
    for (int j = 0; j < 8; j++)
        #pragma unroll
        for (int q = 0; q < 4; q++) acc1[j][q] = 0.f;
    float sqA = 0.f, sqB = 0.f;

    // prefetch H chunk 0 (16 float2: [kk][fa0,fa1,fb0,fb1])
    float2 pf[16];
    {
        const int cb = 2 * tq;
        #pragma unroll
        for (int kk = 0; kk < 4; kk++) {
            int c0 = cb + 16 * kk;
            pf[4 * kk + 0] = *(const float2*)(hA + c0);
            pf[4 * kk + 1] = *(const float2*)(hA + c0 + 8);
            pf[4 * kk + 2] = *(const float2*)(hB + c0);
            pf[4 * kk + 3] = *(const float2*)(hB + c0 + 8);
        }
    }

    // ======== GEMM1: acc1 = H * P, K = 1024 (3-term split) ========
    for (int ch = 0; ch < NCH; ch++) {
        CP_WAIT0;
        __syncthreads();
        const int buf = ch & 1;
        if (ch + 1 < NCH) {
            const uint4* src = g_PP + (ch + 1) * 1024;
            #pragma unroll
            for (int q = 0; q < 4; q++)
                cpa16(sbase + (((buf ^ 1) * 1024 + t + 256 * q) * 16), src + t + 256 * q);
            CP_COMMIT;
        }
        uint32_t ah[4][4], al[4][4];
        #pragma unroll
        for (int kk = 0; kk < 4; kk++) {
            float2 fa0 = pf[4 * kk + 0], fa1 = pf[4 * kk + 1];
            float2 fb0 = pf[4 * kk + 2], fb1 = pf[4 * kk + 3];
            sqA = fmaf(fa0.x, fa0.x, fmaf(fa0.y, fa0.y, fmaf(fa1.x, fa1.x, fmaf(fa1.y, fa1.y, sqA))));
            sqB = fmaf(fb0.x, fb0.x, fmaf(fb0.y, fb0.y, fmaf(fb1.x, fb1.x, fmaf(fb1.y, fb1.y, sqB))));
            split2(fa0.x, fa0.y, ah[kk][0], al[kk][0]);
            split2(fb0.x, fb0.y, ah[kk][1], al[kk][1]);
            split2(fa1.x, fa1.y, ah[kk][2], al[kk][2]);
            split2(fb1.x, fb1.y, ah[kk][3], al[kk][3]);
        }
        if (ch + 1 < NCH) {
            const int cb = (ch + 1) * 64 + 2 * tq;
            #pragma unroll
            for (int kk = 0; kk < 4; kk++) {
                int c0 = cb + 16 * kk;
                pf[4 * kk + 0] = *(const float2*)(hA + c0);
                pf[4 * kk + 1] = *(const float2*)(hA + c0 + 8);
                pf[4 * kk + 2] = *(const float2*)(hB + c0);
                pf[4 * kk + 3] = *(const float2*)(hB + c0 + 8);
            }
        }
        // mma: j-pair interleaved so consecutive mma hit different accumulators
        #pragma unroll
        for (int kk = 0; kk < 4; kk++)
            #pragma unroll
            for (int j = 0; j < 8; j += 2) {
                uint4 b0 = Bs[buf * 1024 + (kk * 8 + j) * 32 + lane];
                uint4 b1 = Bs[buf * 1024 + (kk * 8 + j + 1) * 32 + lane];
                mma_bf16(acc1[j],     ah[kk][0], ah[kk][1], ah[kk][2], ah[kk][3], b0.x, b0.y);
                mma_bf16(acc1[j + 1], ah[kk][0], ah[kk][1], ah[kk][2], ah[kk][3], b1.x, b1.y);
                mma_bf16(acc1[j],     ah[kk][0], ah[kk][1], ah[kk][2], ah[kk][3], b0.z, b0.w);
                mma_bf16(acc1[j + 1], ah[kk][0], ah[kk][1], ah[kk][2], ah[kk][3], b1.z, b1.w);
                mma_bf16(acc1[j],     al[kk][0], al[kk][1], al[kk][2], al[kk][3], b0.x, b0.y);
                mma_bf16(acc1[j + 1], al[kk][0], al[kk][1], al[kk][2], al[kk][3], b1.x, b1.y);
            }
    }

    // old-norm^2 per row (reduce over tq lanes)
    sqA += __shfl_xor_sync(~0u, sqA, 1); sqA += __shfl_xor_sync(~0u, sqA, 2);
    sqB += __shfl_xor_sync(~0u, sqB, 1); sqB += __shfl_xor_sync(~0u, sqB, 2);

    __syncthreads();   // all warps done with GEMM1 Bs

    // prologue: stage GEMM2 W chunk 0 -> buf0 (2048 uint4)
    #pragma unroll
    for (int q = 0; q < 8; q++)
        cpa16(sbase + (t + 256 * q) * 16, g_WP + t + 256 * q);
    CP_COMMIT;

    // ---- repack acc1 (C frags) into GEMM2 A frags (hi + lo) ----
    uint32_t a2h[4][4], a2l[4][4];
    #pragma unroll
    for (int kk = 0; kk < 4; kk++) {
        split2(acc1[2 * kk][0],     acc1[2 * kk][1],     a2h[kk][0], a2l[kk][0]);
        split2(acc1[2 * kk][2],     acc1[2 * kk][3],     a2h[kk][1], a2l[kk][1]);
        split2(acc1[2 * kk + 1][0], acc1[2 * kk + 1][1], a2h[kk][2], a2l[kk][2]);
        split2(acc1[2 * kk + 1][2], acc1[2 * kk + 1][3], a2h[kk][3], a2l[kk][3]);
    }

    // ---- d3 = b * Minv; dot = b . d3; scales ----
    float dA = 0.f, dB = 0.f;
    #pragma unroll
    for (int jh = 0; jh < 2; jh++) {
        float accd[4][4];
        #pragma unroll
        for (int j = 0; j < 4; j++)
            #pragma unroll
            for (int q = 0; q < 4; q++) accd[j][q] = 0.f;
        #pragma unroll
        for (int kk = 0; kk < 4; kk++)
            #pragma unroll
            for (int j = 0; j < 4; j += 2) {
                uint4 b0 = g_MP[((jh * 4 + j) * 4 + kk) * 32 + lane];
                uint4 b1 = g_MP[((jh * 4 + j + 1) * 4 + kk) * 32 + lane];
                mma_bf16(accd[j],     a2h[kk][0], a2h[kk][1], a2h[kk][2], a2h[kk][3], b0.x, b0.y);
                mma_bf16(accd[j + 1], a2h[kk][0], a2h[kk][1], a2h[kk][2], a2h[kk][3], b1.x, b1.y);
                mma_bf16(accd[j],     a2h[kk][0], a2h[kk][1], a2h[kk][2], a2h[kk][3], b0.z, b0.w);
                mma_bf16(accd[j + 1], a2h[kk][0], a2h[kk][1], a2h[kk][2], a2h[kk][3], b1.z, b1.w);
                mma_bf16(accd[j],     a2l[kk][0], a2l[kk][1], a2l[kk][2], a2l[kk][3], b0.x, b0.y);
                mma_bf16(accd[j + 1], a2l[kk][0], a2l[kk][1], a2l[kk][2], a2l[kk][3], b1.x, b1.y);
            }
        #pragma unroll
        for (int j = 0; j < 4; j++) {
            int jj = jh * 4 + j;
            dA = fmaf(acc1[jj][0], accd[j][0], dA); dA = fmaf(acc1[jj][1], accd[j][1], dA);
            dB = fmaf(acc1[jj][2], accd[j][2], dB); dB = fmaf(acc1[jj][3], accd[j][3], dB);
        }
    }
    dA += __shfl_xor_sync(~0u, dA, 1); dA += __shfl_xor_sync(~0u, dA, 2);
    dB += __shfl_xor_sync(~0u, dB, 1); dB += __shfl_xor_sync(~0u, dB, 2);
    const float scA = sqrtf(sqA / fmaxf(sqA - dA, sqA * 1e-12f));
    const float scB = sqrtf(sqB / fmaxf(sqB - dB, sqB * 1e-12f));

    // ======== GEMM2 + fused epilogue: out = (H - b*Wt) * scale ========
    float* pA = out + rowA * FD;
    float* pB = out + rowB * FD;
    const bool fA = ((rowA & 4095) == 0);
    const bool fB = ((rowB & 4095) == 0);

    for (int nc = 0; nc < 8; nc++) {
        CP_WAIT0;
        __syncthreads();
        const int buf = nc & 1;
        if (nc + 1 < 8) {
            const uint4* src = g_WP + (nc + 1) * 2048;
            #pragma unroll
            for (int q = 0; q < 8; q++)
                cpa16(sbase + (((buf ^ 1) * 2048 + t + 256 * q) * 16), src + t + 256 * q);
            CP_COMMIT;
        }
        #pragma unroll
        for (int half = 0; half < 2; half++) {
            float2 h0[8], h1[8];
            #pragma unroll
            for (int jl = 0; jl < 8; jl++) {
                int col = nc * 128 + (half * 8 + jl) * 8 + 2 * tq;
                h0[jl] = *(const float2*)(hA + col);
                h1[jl] = *(const float2*)(hB + col);
            }
            float acc2[8][4];
            #pragma unroll
            for (int jl = 0; jl < 8; jl++)
                #pragma unroll
                for (int q = 0; q < 4; q++) acc2[jl][q] = 0.f;
            #pragma unroll
            for (int kk = 0; kk < 4; kk++)
                #pragma unroll
                for (int jl = 0; jl < 8; jl += 2) {
                    uint4 b0 = Bs[buf * 2048 + ((half * 8 + jl) * 4 + kk) * 32 + lane];
                    uint4 b1 = Bs[buf * 2048 + ((half * 8 + jl + 1) * 4 + kk) * 32 + lane];
                    mma_bf16(acc2[jl],     a2h[kk][0], a2h[kk][1], a2h[kk][2], a2h[kk][3], b0.x, b0.y);
                    mma_bf16(acc2[jl + 1], a2h[kk][0], a2h[kk][1], a2h[kk][2], a2h[kk][3], b1.x, b1.y);
                    mma_bf16(acc2[jl],     a2h[kk][0], a2h[kk][1], a2h[kk][2], a2h[kk][3], b0.z, b0.w);
                    mma_bf16(acc2[jl + 1], a2h[kk][0], a2h[kk][1], a2h[kk][2], a2h[kk][3], b1.z, b1.w);
                    mma_bf16(acc2[jl],     a2l[kk][0], a2l[kk][1], a2l[kk][2], a2l[kk][3], b0.x, b0.y);
                    mma_bf16(acc2[jl + 1], a2l[kk][0], a2l[kk][1], a2l[kk][2], a2l[kk][3], b1.x, b1.y);
                }
            #pragma unroll
            for (int jl = 0; jl < 8; jl++) {
                int col = nc * 128 + (half * 8 + jl) * 8 + 2 * tq;
                float2 o0, o1;
                o0.x = fA ? h0[jl].x : (h0[jl].x - acc2[jl][0]) * scA;
                o0.y = fA ? h0[jl].y : (h0[jl].y - acc2[jl][1]) * scA;
                o1.x = fB ? h1[jl].x : (h1[jl].x - acc2[jl][2]) * scB;
                o1.y = fB ? h1[jl].y : (h1[jl].y - acc2[jl][3]) * scB;
                __stcs((float2*)(pA + col), o0);
                __stcs((float2*)(pB + col), o1);
            }
        }
    }
}

extern "C" void kernel_launch(void* const* d_in, const int* in_sizes, int n_in,
                              void* d_out, int out_size) {
    const float* hs = (const float*)d_in[0];
    const float* probe = (const float*)d_in[1];
    float* out = (float*)d_out;

    k_prep1<<<64, 256>>>(probe);
    k_inv<<<1, 64>>>();
    k_w<<<128, 512>>>(probe);

    cudaFuncSetAttribute(k_main, cudaFuncAttributeMaxDynamicSharedMemorySize, SMEM_BYTES);
    int rows = in_sizes[0] / FD;            // 32768
    k_main<<<rows / MT, 256, SMEM_BYTES>>>(hs, out);
}

// round 10
// speedup vs baseline: 1.4596x; 1.4596x over previous
#include <cuda_runtime.h>
#include <cstdint>

#define FD 1024
#define RD 64
#define MT 128
#define NCH 16          // GEMM1 chunks of 64 cols

// ---------------- device scratch ----------------
__device__ float g_Gp[8][RD * RD];      // partial Gram matrices
__device__ float g_Minv[RD * RD];
__device__ uint4 g_PP[64 * 8 * 32];     // GEMM1 B frags: [kstep][ntile][lane] {h0,h1,l0,l1}
__device__ uint4 g_WP[128 * 4 * 32];    // GEMM2 B frags: [ntile][kstep][lane]
__device__ uint4 g_MP[8 * 4 * 32];      // d3 B frags (Minv)

// ---------------- helpers ----------------
__device__ __forceinline__ void split2(float x, float y, uint32_t& hi, uint32_t& lo) {
    asm("cvt.rn.bf16x2.f32 %0, %1, %2;" : "=r"(hi) : "f"(y), "f"(x));
    float xr = x - __uint_as_float(hi << 16);
    float yr = y - __uint_as_float(hi & 0xffff0000u);
    asm("cvt.rn.bf16x2.f32 %0, %1, %2;" : "=r"(lo) : "f"(yr), "f"(xr));
}

__device__ __forceinline__ void mma_bf16(float* d,
    uint32_t a0, uint32_t a1, uint32_t a2, uint32_t a3,
    uint32_t b0, uint32_t b1) {
    asm volatile("mma.sync.aligned.m16n8k16.row.col.f32.bf16.bf16.f32 "
        "{%0,%1,%2,%3}, {%4,%5,%6,%7}, {%8,%9}, {%0,%1,%2,%3};"
        : "+f"(d[0]), "+f"(d[1]), "+f"(d[2]), "+f"(d[3])
        : "r"(a0), "r"(a1), "r"(a2), "r"(a3), "r"(b0), "r"(b1));
}

__device__ __forceinline__ void cpa16(uint32_t s, const void* g) {
    asm volatile("cp.async.cg.shared.global [%0], [%1], 16;" :: "r"(s), "l"(g));
}
#define CP_COMMIT asm volatile("cp.async.commit_group;" ::: "memory")
#define CP_WAIT0  asm volatile("cp.async.wait_group 0;" ::: "memory")

// ---------------- prep 1: partial gram (blocks 0-7) + pack P (all 64) ----------------
__global__ void k_prep1(const float* __restrict__ probe) {
    __shared__ float Ps[128][68];
    int t = threadIdx.x;
    if (blockIdx.x < 8) {
        int c = blockIdx.x;
        #pragma unroll
        for (int i = 0; i < 8; i++) {
            int idx = t + 256 * i;
            int fl = idx >> 4, r4 = (idx & 15) << 2;
            float4 v = *(const float4*)(probe + (c * 128 + fl) * 64 + r4);
            *(float4*)(&Ps[fl][r4]) = v;
        }
        __syncthreads();
        int ti = (t >> 4) << 2, tj = (t & 15) << 2;
        float acc[4][4];
        #pragma unroll
        for (int a = 0; a < 4; a++)
            #pragma unroll
            for (int b = 0; b < 4; b++) acc[a][b] = 0.f;
        for (int k = 0; k < 128; k++) {
            float av[4], bv[4];
            #pragma unroll
            for (int a = 0; a < 4; a++) av[a] = Ps[k][ti + a];
            #pragma unroll
            for (int b = 0; b < 4; b++) bv[b] = Ps[k][tj + b];
            #pragma unroll
            for (int a = 0; a < 4; a++)
                #pragma unroll
                for (int b = 0; b < 4; b++) acc[a][b] = fmaf(av[a], bv[b], acc[a][b]);
        }
        #pragma unroll
        for (int a = 0; a < 4; a++)
            #pragma unroll
            for (int b = 0; b < 4; b++)
                g_Gp[c][(ti + a) * 64 + tj + b] = acc[a][b];
    }
    // pack P with k-permutation: slot (kk,tq) pairs hold physical k = 16kk+4tq+{0,1} / {2,3}
    {
        int id = blockIdx.x * 256 + t;
        int lane = id & 31, g = lane >> 2, tq = lane & 3;
        int kk = id >> 8, j = (id >> 5) & 7;
        int n = 8 * j + g, k0 = 16 * kk + 4 * tq;
        float p00 = probe[(k0) * 64 + n],     p01 = probe[(k0 + 1) * 64 + n];
        float p10 = probe[(k0 + 2) * 64 + n], p11 = probe[(k0 + 3) * 64 + n];
        uint32_t h0, l0, h1, l1;
        split2(p00, p01, h0, l0);
        split2(p10, p11, h1, l1);
        g_PP[id] = make_uint4(h0, h1, l0, l1);
    }
}

// ---------------- prep 2: parallel Gauss-Jordan (1024 threads) + pack Minv ----------------
__global__ void k_inv() {
    __shared__ float A[64][132];           // 128 cols used, pad to 132
    int t = threadIdx.x;                   // 1024
    int r = t >> 4, cs = t & 15;
    int col0 = cs * 8;
    // load: cols<64 = sum of partials; cols>=64 = identity
    #pragma unroll
    for (int i = 0; i < 8; i++) {
        int col = col0 + i;
        if (col < 64) {
            float s = 0.f;
            #pragma unroll
            for (int p = 0; p < 8; p++) s += g_Gp[p][r * 64 + col];
            A[r][col] = s;
        } else {
            A[r][col] = (col - 64 == r) ? 1.f : 0.f;
        }
    }
    __syncthreads();
    for (int k = 0; k < 64; k++) {
        float inv = 1.f / A[k][k];         // stable since last barrier
        float f = A[r][k];                 // read before any write this iter
        if (r == k) {
            #pragma unroll
            for (int i = 0; i < 8; i++) A[k][col0 + i] *= inv;
        }
        __syncthreads();
        if (r != k) {
            #pragma unroll
            for (int i = 0; i < 8; i++)
                A[r][col0 + i] = fmaf(-f, A[k][col0 + i], A[r][col0 + i]);
        }
        __syncthreads();
    }
    // write Minv (4 entries/thread)
    #pragma unroll
    for (int i = 0; i < 4; i++) {
        int id = t + 1024 * i;
        int rr = id >> 6, jj = id & 63;
        if (i == 0 || id < 4096) g_Minv[rr * 64 + jj] = A[rr][64 + jj];
    }
    // pack g_MP (1024 uint4, one per thread)
    {
        int id = t;
        int lane = id & 31, g = lane >> 2, tq = lane & 3;
        int j = id >> 7, kk = (id >> 5) & 3;
        int n = 8 * j + g, k0 = 16 * kk + 2 * tq;
        float m00 = A[k0][64 + n],     m01 = A[k0 + 1][64 + n];
        float m10 = A[k0 + 8][64 + n], m11 = A[k0 + 9][64 + n];
        uint32_t h0, l0, h1, l1;
        split2(m00, m01, h0, l0);
        split2(m10, m11, h1, l1);
        g_MP[id] = make_uint4(h0, h1, l0, l1);
    }
}

// ---------------- prep 3: W = P*Minv (16 f-rows/block) + pack permuted W frags ----------------
__global__ void k_w(const float* __restrict__ probe) {
    __shared__ float Ms[4096];
    __shared__ float Ps[16][64];
    __shared__ float Ws[16][68];
    int t = threadIdx.x;                   // 1024
    #pragma unroll
    for (int i = 0; i < 4; i++) Ms[t + 1024 * i] = g_Minv[t + 1024 * i];
    {
        int fl = t >> 6, k = t & 63;
        Ps[fl][k] = probe[(blockIdx.x * 16 + fl) * 64 + k];
    }
    __syncthreads();
    {
        int fl = t >> 6, rr = t & 63;
        float acc = 0.f;
        #pragma unroll 16
        for (int k = 0; k < 64; k++) acc = fmaf(Ps[fl][k], Ms[k * 64 + rr], acc);
        Ws[fl][rr] = acc;
    }
    __syncthreads();
    // pack tiles T = 2b and 2b+1; col-slot g of tile T holds physical f = 16b + 4(g>>1) + 2(T&1) + (g&1)
    if (t < 256) {
        int jo = t >> 7, kk = (t >> 5) & 3, lane = t & 31, g = lane >> 2, tq = lane & 3;
        int fl = 4 * (g >> 1) + 2 * jo + (g & 1);
        int r0 = 16 * kk + 2 * tq;
        float w00 = Ws[fl][r0],     w01 = Ws[fl][r0 + 1];
        float w10 = Ws[fl][r0 + 8], w11 = Ws[fl][r0 + 9];
        uint32_t h0, l0, h1, l1;
        split2(w00, w01, h0, l0);
        split2(w10, w11, h1, l1);
        g_WP[(blockIdx.x * 2 + jo) * 128 + kk * 32 + lane] = make_uint4(h0, h1, l0, l1);
    }
}

// ---------------- main kernel ----------------
#define SMEM_WORDS 16448
#define SMEM_BYTES (SMEM_WORDS * 4)

__global__ void __launch_bounds__(256, 2)
k_main(const float* __restrict__ hs, float* __restrict__ out) {
    extern __shared__ uint32_t smw[];
    uint4* Bs = (uint4*)smw;

    const int t = threadIdx.x;
    const int wg = t >> 5, lane = t & 31, g = lane >> 2, tq = lane & 3;
    const size_t g0 = (size_t)blockIdx.x * MT;
    const size_t rowA = g0 + 16 * wg + g, rowB = rowA + 8;
    const float* hA = hs + rowA * FD;
    const float* hB = hs + rowB * FD;

    uint32_t sbase = (uint32_t)__cvta_generic_to_shared(smw);

    // prologue: stage GEMM1 B chunk 0 -> buf0
    #pragma unroll
    for (int q = 0; q < 4; q++)
        cpa16(sbase + (t + 256 * q) * 16, g_PP + t + 256 * q);
    CP_COMMIT;

    float acc1[8][4];
    #pragma unroll
    for (int j = 0; j < 8; j++)
        #pragma unroll
        for (int q = 0; q < 4; q++) acc1[j][q] = 0.f;
    float sqA = 0.f, sqB = 0.f;

    // prefetch H chunk 0: float4 per (kk,row): physical k = 16kk + 4tq .. +3
    float4 pa[4], pb[4];
    #pragma unroll
    for (int kk = 0; kk < 4; kk++) {
        int c0 = 16 * kk + 4 * tq;
        pa[kk] = *(const float4*)(hA + c0);
        pb[kk] = *(const float4*)(hB + c0);
    }

    // ======== GEMM1: acc1 = H * P, K = 1024 (3-term split) ========
    for (int ch = 0; ch < NCH; ch++) {
        CP_WAIT0;
        __syncthreads();
        const int buf = ch & 1;
        if (ch + 1 < NCH) {
            const uint4* src = g_PP + (ch + 1) * 1024;
            #pragma unroll
            for (int q = 0; q < 4; q++)
                cpa16(sbase + (((buf ^ 1) * 1024 + t + 256 * q) * 16), src + t + 256 * q);
            CP_COMMIT;
        }
        uint32_t ah[4][4], al[4][4];
        #pragma unroll
        for (int kk = 0; kk < 4; kk++) {
            float4 a4 = pa[kk], b4 = pb[kk];
            sqA = fmaf(a4.x, a4.x, fmaf(a4.y, a4.y, fmaf(a4.z, a4.z, fmaf(a4.w, a4.w, sqA))));
            sqB = fmaf(b4.x, b4.x, fmaf(b4.y, b4.y, fmaf(b4.z, b4.z, fmaf(b4.w, b4.w, sqB))));
            split2(a4.x, a4.y, ah[kk][0], al[kk][0]);   // a0: k 16kk+4tq+{0,1}
            split2(b4.x, b4.y, ah[kk][1], al[kk][1]);   // a1 (row+8)
            split2(a4.z, a4.w, ah[kk][2], al[kk][2]);   // a2: k 16kk+4tq+{2,3}
            split2(b4.z, b4.w, ah[kk][3], al[kk][3]);   // a3
        }
        if (ch + 1 < NCH) {
            const int cb = (ch + 1) * 64 + 4 * tq;
            #pragma unroll
            for (int kk = 0; kk < 4; kk++) {
                int c0 = cb + 16 * kk;
                pa[kk] = *(const float4*)(hA + c0);
                pb[kk] = *(const float4*)(hB + c0);
            }
        }
        #pragma unroll
        for (int kk = 0; kk < 4; kk++)
            #pragma unroll
            for (int j = 0; j < 8; j += 2) {
                uint4 b0 = Bs[buf * 1024 + (kk * 8 + j) * 32 + lane];
                uint4 b1 = Bs[buf * 1024 + (kk * 8 + j + 1) * 32 + lane];
                mma_bf16(acc1[j],     ah[kk][0], ah[kk][1], ah[kk][2], ah[kk][3], b0.x, b0.y);
                mma_bf16(acc1[j + 1], ah[kk][0], ah[kk][1], ah[kk][2], ah[kk][3], b1.x, b1.y);
                mma_bf16(acc1[j],     ah[kk][0], ah[kk][1], ah[kk][2], ah[kk][3], b0.z, b0.w);
                mma_bf16(acc1[j + 1], ah[kk][0], ah[kk][1], ah[kk][2], ah[kk][3], b1.z, b1.w);
                mma_bf16(acc1[j],     al[kk][0], al[kk][1], al[kk][2], al[kk][3], b0.x, b0.y);
                mma_bf16(acc1[j + 1], al[kk][0], al[kk][1], al[kk][2], al[kk][3], b1.x, b1.y);
            }
    }

    sqA += __shfl_xor_sync(~0u, sqA, 1); sqA += __shfl_xor_sync(~0u, sqA, 2);
    sqB += __shfl_xor_sync(~0u, sqB, 1); sqB += __shfl_xor_sync(~0u, sqB, 2);

    __syncthreads();

    // prologue: stage GEMM2 W chunk 0 -> buf0 (2048 uint4)
    #pragma unroll
    for (int q = 0; q < 8; q++)
        cpa16(sbase + (t + 256 * q) * 16, g_WP + t + 256 * q);
    CP_COMMIT;

    // ---- repack acc1 (C frags) into GEMM2 A frags ----
    uint32_t a2h[4][4], a2l[4][4];
    #pragma unroll
    for (int kk = 0; kk < 4; kk++) {
        split2(acc1[2 * kk][0],     acc1[2 * kk][1],     a2h[kk][0], a2l[kk][0]);
        split2(acc1[2 * kk][2],     acc1[2 * kk][3],     a2h[kk][1], a2l[kk][1]);
        split2(acc1[2 * kk + 1][0], acc1[2 * kk + 1][1], a2h[kk][2], a2l[kk][2]);
        split2(acc1[2 * kk + 1][2], acc1[2 * kk + 1][3], a2h[kk][3], a2l[kk][3]);
    }

    // ---- d3 = b * Minv; dot = b . d3; scales ----
    float dA = 0.f, dB = 0.f;
    #pragma unroll
    for (int jh = 0; jh < 2; jh++) {
        float accd[4][4];
        #pragma unroll
        for (int j = 0; j < 4; j++)
            #pragma unroll
            for (int q = 0; q < 4; q++) accd[j][q] = 0.f;
        #pragma unroll
        for (int kk = 0; kk < 4; kk++)
            #pragma unroll
            for (int j = 0; j < 4; j += 2) {
                uint4 b0 = g_MP[((jh * 4 + j) * 4 + kk) * 32 + lane];
                uint4 b1 = g_MP[((jh * 4 + j + 1) * 4 + kk) * 32 + lane];
                mma_bf16(accd[j],     a2h[kk][0], a2h[kk][1], a2h[kk][2], a2h[kk][3], b0.x, b0.y);
                mma_bf16(accd[j + 1], a2h[kk][0], a2h[kk][1], a2h[kk][2], a2h[kk][3], b1.x, b1.y);
                mma_bf16(accd[j],     a2h[kk][0], a2h[kk][1], a2h[kk][2], a2h[kk][3], b0.z, b0.w);
                mma_bf16(accd[j + 1], a2h[kk][0], a2h[kk][1], a2h[kk][2], a2h[kk][3], b1.z, b1.w);
                mma_bf16(accd[j],     a2l[kk][0], a2l[kk][1], a2l[kk][2], a2l[kk][3], b0.x, b0.y);
                mma_bf16(accd[j + 1], a2l[kk][0], a2l[kk][1], a2l[kk][2], a2l[kk][3], b1.x, b1.y);
            }
        #pragma unroll
        for (int j = 0; j < 4; j++) {
            int jj = jh * 4 + j;
            dA = fmaf(acc1[jj][0], accd[j][0], dA); dA = fmaf(acc1[jj][1], accd[j][1], dA);
            dB = fmaf(acc1[jj][2], accd[j][2], dB); dB = fmaf(acc1[jj][3], accd[j][3], dB);
        }
    }
    dA += __shfl_xor_sync(~0u, dA, 1); dA += __shfl_xor_sync(~0u, dA, 2);
    dB += __shfl_xor_sync(~0u, dB, 1); dB += __shfl_xor_sync(~0u, dB, 2);
    const float scA = sqrtf(sqA / fmaxf(sqA - dA, sqA * 1e-12f));
    const float scB = sqrtf(sqB / fmaxf(sqB - dB, sqB * 1e-12f));

    // ======== GEMM2 + fused epilogue: out = (H - b*Wt) * scale ========
    float* pA = out + rowA * FD;
    float* pB = out + rowB * FD;
    const bool fA = ((rowA & 4095) == 0);
    const bool fB = ((rowB & 4095) == 0);

    for (int nc = 0; nc < 8; nc++) {
        CP_WAIT0;
        __syncthreads();
        const int buf = nc & 1;
        if (nc + 1 < 8) {
            const uint4* src = g_WP + (nc + 1) * 2048;
            #pragma unroll
            for (int q = 0; q < 8; q++)
                cpa16(sbase + (((buf ^ 1) * 2048 + t + 256 * q) * 16), src + t + 256 * q);
            CP_COMMIT;
        }
        #pragma unroll
        for (int half = 0; half < 2; half++) {
            // H re-reads: float4 per tile-pair (physical col = nc*128 + half*64 + 16p + 4tq)
            float4 hv0[4], hv1[4];
            #pragma unroll
            for (int p = 0; p < 4; p++) {
                int col = nc * 128 + half * 64 + 16 * p + 4 * tq;
                hv0[p] = *(const float4*)(hA + col);
                hv1[p] = *(const float4*)(hB + col);
            }
            float acc2[8][4];
            #pragma unroll
            for (int jl = 0; jl < 8; jl++)
                #pragma unroll
                for (int q = 0; q < 4; q++) acc2[jl][q] = 0.f;
            #pragma unroll
            for (int kk = 0; kk < 4; kk++)
                #pragma unroll
                for (int jl = 0; jl < 8; jl += 2) {
                    uint4 b0 = Bs[buf * 2048 + ((half * 8 + jl) * 4 + kk) * 32 + lane];
                    uint4 b1 = Bs[buf * 2048 + ((half * 8 + jl + 1) * 4 + kk) * 32 + lane];
                    mma_bf16(acc2[jl],     a2h[kk][0], a2h[kk][1], a2h[kk][2], a2h[kk][3], b0.x, b0.y);
                    mma_bf16(acc2[jl + 1], a2h[kk][0], a2h[kk][1], a2h[kk][2], a2h[kk][3], b1.x, b1.y);
                    mma_bf16(acc2[jl],     a2h[kk][0], a2h[kk][1], a2h[kk][2], a2h[kk][3], b0.z, b0.w);
                    mma_bf16(acc2[jl + 1], a2h[kk][0], a2h[kk][1], a2h[kk][2], a2h[kk][3], b1.z, b1.w);
                    mma_bf16(acc2[jl],     a2l[kk][0], a2l[kk][1], a2l[kk][2], a2l[kk][3], b0.x, b0.y);
                    mma_bf16(acc2[jl + 1], a2l[kk][0], a2l[kk][1], a2l[kk][2], a2l[kk][3], b1.x, b1.y);
                }
            // stores: tile-pair p covers physical cols [.. +16p+4tq, +3]:
            //   {acc2[2p][0], acc2[2p][1], acc2[2p+1][0], acc2[2p+1][1]} for rowA; [2],[3] rowB
            #pragma unroll
            for (int p = 0; p < 4; p++) {
                int col = nc * 128 + half * 64 + 16 * p + 4 * tq;
                float4 o0, o1;
                o0.x = (hv0[p].x - acc2[2 * p][0]) * scA;
                o0.y = (hv0[p].y - acc2[2 * p][1]) * scA;
                o0.z = (hv0[p].z - acc2[2 * p + 1][0]) * scA;
                o0.w = (hv0[p].w - acc2[2 * p + 1][1]) * scA;
                o1.x = (hv1[p].x - acc2[2 * p][2]) * scB;
                o1.y = (hv1[p].y - acc2[2 * p][3]) * scB;
                o1.z = (hv1[p].z - acc2[2 * p + 1][2]) * scB;
                o1.w = (hv1[p].w - acc2[2 * p + 1][3]) * scB;
                if (fA) o0 = hv0[p];
                if (fB) o1 = hv1[p];
                __stcs((float4*)(pA + col), o0);
                __stcs((float4*)(pB + col), o1);
            }
        }
    }
}

extern "C" void kernel_launch(void* const* d_in, const int* in_sizes, int n_in,
                              void* d_out, int out_size) {
    const float* hs = (const float*)d_in[0];
    const float* probe = (const float*)d_in[1];
    float* out = (float*)d_out;

    k_prep1<<<64, 256>>>(probe);
    k_inv<<<1, 1024>>>();
    k_w<<<64, 1024>>>(probe);

    cudaFuncSetAttribute(k_main, cudaFuncAttributeMaxDynamicSharedMemorySize, SMEM_BYTES);
    int rows = in_sizes[0] / FD;            // 32768
    k_main<<<rows / MT, 256, SMEM_BYTES>>>(hs, out);
}